// round 9
// baseline (speedup 1.0000x reference)
#include <cuda_runtime.h>

#define T_STEPS 50
#define BATCH   256
#define NS      64
#define NC      32
#define NN      96
#define NTHR    256

typedef unsigned long long ull;

__device__ float g_K[(size_t)T_STEPS * BATCH * NC * NS];   // [t][b][32][64]
__device__ float g_k[(size_t)T_STEPS * BATCH * NC];        // [t][b][32]

// ---- shared memory layout (floats) ----
#define OFF_V    0                       // V carry, 64 x 68 (symmetric)
#define OFF_F    (OFF_V  + 64*68)        // F tile, 64 x 96
#define OFF_Q    (OFF_F  + 6144)         // Q, 96 x 96 FULL (mirrored)
#define OFF_WB   (OFF_Q  + 9216)         // W (64x96) -- dead after phase 2
#define OFF_LI   (OFF_WB)                // Linv 32x33       (overlaps W)
#define OFF_Z    (OFF_LI + 1056)         // scratch 32x65    (overlaps W; fwd K buf)
#define OFF_K    (OFF_Z  + 2080)         // K 32x64          (overlaps W)
#define OFF_v    (OFF_WB + 6144)         // v carry, 64
#define OFF_q    (OFF_v  + 64)           // q part A, 96
#define OFF_q2   (OFF_q  + 96)           // q part B (F^T t), 96
#define OFF_xu   (OFF_q2 + 96)           // xut, 96
#define OFF_kv   (OFF_xu + 96)           // k vec, 32
#define OFF_T    (OFF_kv + 32)           // t = v - V z, 64
#define OFF_id   (OFF_T  + 64)           // inv diag, 32
#define OFF_zv   (OFF_id + 32)           // z = F xut, 64
#define OFF_L    (OFF_zv + 64)           // Cholesky 32x33 (DEDICATED)
#define OFF_FWD  (OFF_L  + 1056)         // forward-pass arrays (480)
#define SMEM_FLOATS (OFF_FWD + 480)
#define SMEM_BYTES  (SMEM_FLOATS * 4)

// ---- packed fp32x2 helpers (SASS FFMA2 path) ----
__device__ __forceinline__ ull pk2(float lo, float hi) {
    ull r; asm("mov.b64 %0, {%1, %2};" : "=l"(r) : "f"(lo), "f"(hi)); return r;
}
__device__ __forceinline__ ull dup2(float x) { return pk2(x, x); }
__device__ __forceinline__ void upk2(float& lo, float& hi, ull v) {
    asm("mov.b64 {%0, %1}, %2;" : "=f"(lo), "=f"(hi) : "l"(v));
}
__device__ __forceinline__ void fma2(ull& d, ull a, ull b) {
    asm("fma.rn.f32x2 %0, %2, %3, %1;" : "=l"(d) : "l"(d), "l"(a), "l"(b));
}

__global__ __launch_bounds__(NTHR, 2)
void lqr_kernel(const float* __restrict__ x_init,
                const float* __restrict__ Cg,
                const float* __restrict__ cg,
                const float* __restrict__ Fg,
                const float* __restrict__ cxg,
                const float* __restrict__ cug,
                float* __restrict__ out)
{
    extern __shared__ float sm[];
    const int b   = blockIdx.x;
    const int tid = threadIdx.x;

    float* sV  = sm + OFF_V;
    float* sF  = sm + OFF_F;
    float* sQ  = sm + OFF_Q;
    float* sW  = sm + OFF_WB;
    float* sLi = sm + OFF_LI;
    float* sZ  = sm + OFF_Z;
    float* sK  = sm + OFF_K;
    float* sv  = sm + OFF_v;
    float* sq  = sm + OFF_q;
    float* sq2 = sm + OFF_q2;
    float* sxu = sm + OFF_xu;
    float* skv = sm + OFF_kv;
    float* st  = sm + OFF_T;
    float* sid = sm + OFF_id;
    float* sz  = sm + OFF_zv;
    float* sL  = sm + OFF_L;

    // Phase-2 job map: 6x8 tiles over 96x96, lower blocks (6bi+5 >= 8bj): 108 jobs.
    int p2bi = -1, p2bj = 0;
    {
        int idx = tid;
        #pragma unroll
        for (int r = 0; r < 16; ++r) {
            int cnt = (6 * r + 5) / 8 + 1;
            if (idx < cnt && p2bi < 0) { p2bi = r; p2bj = idx; }
            if (p2bi < 0) idx -= cnt;
        }
    }
    const bool p2a = (p2bi >= 0);

    // Phase-6 pair-tile map: 4x4 tiles on 64x64, (bi>=bj): 136 jobs.
    int u7bi = -1, u7bj = 0;
    {
        int idx = tid;
        #pragma unroll
        for (int r = 0; r < 16; ++r) {
            int cnt = r + 1;
            if (idx < cnt && u7bi < 0) { u7bi = r; u7bj = idx; }
            if (u7bi < 0) idx -= cnt;
        }
    }

    // ---------------- init ----------------
    for (int i = tid; i < 64 * 68; i += NTHR) sV[i] = 0.f;
    if (tid < NS) sv[tid] = 0.f;
    {
        const float* Fsrc = Fg + ((size_t)(T_STEPS - 1) * BATCH + b) * (NS * NN);
        for (int i = tid; i < NS * NN; i += NTHR) sF[i] = Fsrc[i];
    }
    __syncthreads();

    // ================= BACKWARD RICCATI SCAN =================
    for (int t = T_STEPS - 1; t >= 0; --t) {
        const size_t tb = (size_t)t * BATCH + b;

        // ---- P1: W = V @ F (64x96), 4x12 FFMA2 tiles (tid<128)
        //      | xut -> z = F@xut -> t = v - V@z  (tid>=128, internal bars) ----
        if (tid < 128) {
            const int i0 = (tid >> 3) * 4;      // 16 row-blocks
            const int j0 = (tid & 7) * 12;      // 8 col-blocks
            ull acc[4][6];
            #pragma unroll
            for (int u = 0; u < 4; ++u)
                #pragma unroll
                for (int p = 0; p < 6; ++p) acc[u][p] = 0ull;
            #pragma unroll 2
            for (int a = 0; a < 64; ++a) {
                float4 b0 = *reinterpret_cast<const float4*>(&sF[a * 96 + j0]);
                float4 b1 = *reinterpret_cast<const float4*>(&sF[a * 96 + j0 + 4]);
                float4 b2 = *reinterpret_cast<const float4*>(&sF[a * 96 + j0 + 8]);
                ull bv[6] = { pk2(b0.x, b0.y), pk2(b0.z, b0.w),
                              pk2(b1.x, b1.y), pk2(b1.z, b1.w),
                              pk2(b2.x, b2.y), pk2(b2.z, b2.w) };
                float4 av = *reinterpret_cast<const float4*>(&sV[a * 68 + i0]); // V sym
                ull a0 = dup2(av.x), a1 = dup2(av.y), a2 = dup2(av.z), a3 = dup2(av.w);
                #pragma unroll
                for (int p = 0; p < 6; ++p) {
                    fma2(acc[0][p], a0, bv[p]); fma2(acc[1][p], a1, bv[p]);
                    fma2(acc[2][p], a2, bv[p]); fma2(acc[3][p], a3, bv[p]);
                }
            }
            #pragma unroll
            for (int u = 0; u < 4; ++u)
                #pragma unroll
                for (int p = 0; p < 6; ++p)
                    *reinterpret_cast<ull*>(&sW[(i0 + u) * 96 + j0 + 2 * p]) = acc[u][p];
        } else {
            const int idx = tid - 128;
            if (idx < NS)            sxu[idx] = cxg[tb * NS + idx];
            else if (idx < NN)       sxu[idx] = cug[tb * NC + (idx - NS)];
            asm volatile("bar.sync 3, 128;" ::: "memory");   // warps 4-7 only
            if (idx < 64) {
                const int o = idx;
                int ro = (3 * o) % 96;
                float s0 = 0.f, s1 = 0.f;
                #pragma unroll 8
                for (int j = 0; j < 96; j += 2) {
                    int j0i = j + ro;     if (j0i >= 96) j0i -= 96;
                    int j1i = j + 1 + ro; if (j1i >= 96) j1i -= 96;
                    s0 += sF[o * 96 + j0i] * sxu[j0i];
                    s1 += sF[o * 96 + j1i] * sxu[j1i];
                }
                sz[o] = s0 + s1;
            }
            asm volatile("bar.sync 3, 128;" ::: "memory");
            if (idx < 64) {
                const int a = idx;
                const int ra = (3 * a) & 63;
                float s0 = 0.f, s1 = 0.f;
                #pragma unroll 8
                for (int j = 0; j < 64; j += 2) {
                    int j0i = (j + ra) & 63;
                    int j1i = (j + 1 + ra) & 63;
                    s0 += sV[a * 68 + j0i] * sz[j0i];
                    s1 += sV[a * 68 + j1i] * sz[j1i];
                }
                st[a] = sv[a] - s0 - s1;
            }
        }
        __syncthreads();

        // ---- P2: Q = C + F^T W (lower 6x8 + mirror), dual-write Quu -> sL ----
        if (p2a) {
            const int i0 = p2bi * 6, j0 = p2bj * 8;
            const float* Crow = Cg + tb * (NN * NN);
            float4 cL[6][2];
            #pragma unroll
            for (int r = 0; r < 6; ++r) {
                cL[r][0] = *reinterpret_cast<const float4*>(&Crow[(i0 + r) * 96 + j0]);
                cL[r][1] = *reinterpret_cast<const float4*>(&Crow[(i0 + r) * 96 + j0 + 4]);
            }
            ull acc[3][8];
            #pragma unroll
            for (int m = 0; m < 3; ++m)
                #pragma unroll
                for (int v = 0; v < 8; ++v) acc[m][v] = 0ull;
            #pragma unroll 2
            for (int a = 0; a < 64; ++a) {
                ull am[3];
                #pragma unroll
                for (int m = 0; m < 3; ++m)
                    am[m] = *reinterpret_cast<const ull*>(&sF[a * 96 + i0 + 2 * m]);
                float4 w0 = *reinterpret_cast<const float4*>(&sW[a * 96 + j0]);
                float4 w1 = *reinterpret_cast<const float4*>(&sW[a * 96 + j0 + 4]);
                ull wd[8] = { dup2(w0.x), dup2(w0.y), dup2(w0.z), dup2(w0.w),
                              dup2(w1.x), dup2(w1.y), dup2(w1.z), dup2(w1.w) };
                #pragma unroll
                for (int m = 0; m < 3; ++m)
                    #pragma unroll
                    for (int v = 0; v < 8; ++v) fma2(acc[m][v], am[m], wd[v]);
            }
            #pragma unroll
            for (int m = 0; m < 3; ++m) {
                float r0[8], r1[8];
                #pragma unroll
                for (int v = 0; v < 8; ++v) upk2(r0[v], r1[v], acc[m][v]);
                const float* c0a = &cL[2 * m][0].x;
                const float* c1a = &cL[2 * m + 1][0].x;
                #pragma unroll
                for (int v = 0; v < 8; ++v) {
                    const int i = i0 + 2 * m, j = j0 + v;
                    float val = r0[v] + c0a[v];
                    if (i >= j) {
                        sQ[i * 96 + j] = val;
                        if (j >= 64) sL[(i - 64) * 33 + (j - 64)] = val;
                    }
                    if (i > j) {
                        sQ[j * 96 + i] = val;
                        if (j >= 64) sL[(j - 64) * 33 + (i - 64)] = val;
                    }
                }
                #pragma unroll
                for (int v = 0; v < 8; ++v) {
                    const int i = i0 + 2 * m + 1, j = j0 + v;
                    float val = r1[v] + c1a[v];
                    if (i >= j) {
                        sQ[i * 96 + j] = val;
                        if (j >= 64) sL[(i - 64) * 33 + (j - 64)] = val;
                    }
                    if (i > j) {
                        sQ[j * 96 + i] = val;
                        if (j >= 64) sL[(j - 64) * 33 + (i - 64)] = val;
                    }
                }
            }
        }
        __syncthreads();

        // ---- P3: qA = c + Q@xut (0-95) | C L2-prefetch (96-127)
        //          | Chol+Linv (warp 4) | qB = F^T t (160-255) ----
        if (tid < NN) {
            const int i = tid;
            float cval = cg[tb * NN + i];
            float s0 = 0.f, s1 = 0.f, s2 = 0.f, s3 = 0.f;
            #pragma unroll 8
            for (int j = 0; j < 96; j += 4) {
                int j0i = j + i;     if (j0i >= 96) j0i -= 96;
                int j1i = j + 1 + i; if (j1i >= 96) j1i -= 96;
                int j2i = j + 2 + i; if (j2i >= 96) j2i -= 96;
                int j3i = j + 3 + i; if (j3i >= 96) j3i -= 96;
                s0 += sQ[i * 96 + j0i] * sxu[j0i];
                s1 += sQ[i * 96 + j1i] * sxu[j1i];
                s2 += sQ[i * 96 + j2i] * sxu[j2i];
                s3 += sQ[i * 96 + j3i] * sxu[j3i];
            }
            sq[i] = cval + (s0 + s1) + (s2 + s3);
        } else if (tid < 128) {
            if (t > 0) {   // prefetch next step's C tile into L2
                const float* Cn = Cg + (tb - BATCH) * (size_t)(NN * NN);
                #pragma unroll
                for (int r = 0; r < 9; ++r) {
                    int line = (tid - 96) + r * 32;     // 288 x 128B lines
                    asm volatile("prefetch.global.L2 [%0];"
                                 :: "l"(Cn + line * 32) : "memory");
                }
            }
        } else if (tid < 160) {
            const int r = tid - 128;
            float Lr[32];
            #pragma unroll
            for (int kk = 0; kk < 32; ++kk) Lr[kk] = sL[r * 33 + kk];
            #pragma unroll
            for (int j = 0; j < 32; ++j) {
                float s = Lr[j];
                #pragma unroll
                for (int kk = 0; kk < j; ++kk) s -= Lr[kk] * sL[j * 33 + kk];
                float d = sqrtf(__shfl_sync(0xffffffffu, s, j));
                float val = (r == j) ? d : s / d;
                Lr[j] = val;
                if (r >= j) sL[r * 33 + j] = val;
                if (r == j) sid[j] = 1.0f / d;
                __syncwarp();
            }
            // triangular inverse: lane r computes column r of Linv
            {
                float x[32];
                #pragma unroll
                for (int j = 0; j < 32; ++j) {
                    float s = (j == r) ? 1.0f : 0.0f;
                    #pragma unroll
                    for (int kk = 0; kk < j; ++kk) s -= sL[j * 33 + kk] * x[kk];
                    x[j] = (j < r) ? 0.0f : s * sid[j];
                    sLi[j * 33 + r] = x[j];
                }
            }
        } else {
            const int i = tid - 160;
            float f0 = 0.f, f1 = 0.f;
            #pragma unroll 8
            for (int a = 0; a < 64; a += 2) {
                f0 += sF[a * 96 + i] * st[a];
                f1 += sF[(a + 1) * 96 + i] * st[a + 1];
            }
            sq2[i] = f0 + f1;
        }
        __syncthreads();

        // ---- P4 (merged solve): K = -Linv^T (Linv @ [Q_ux | q_u])
        //      one phase, fused z; threads 0-129 | F-prefetch (130-255) ----
        if (tid < 130) {
            const int c  = tid % 65;
            const int r0 = (tid / 65) * 16;
            float Rv[32];
            #pragma unroll
            for (int j = 0; j < 32; ++j)
                Rv[j] = (c < 64) ? sQ[(64 + j) * 96 + c]
                                 : (sq[64 + j] + sq2[64 + j]);
            float acc[16];
            #pragma unroll
            for (int i = 0; i < 16; ++i) acc[i] = 0.f;
            #pragma unroll
            for (int r = 0; r < 32; ++r) {
                float zr = 0.f;                          // z_r = (Linv @ R)_r
                #pragma unroll
                for (int j = 0; j <= r; ++j) zr += sLi[r * 33 + j] * Rv[j];
                #pragma unroll
                for (int i = 0; i < 16; ++i)             // K rows r0..r0+15
                    if (r0 + i <= r) acc[i] += sLi[r * 33 + (r0 + i)] * zr;
            }
            if (c < 64) {
                float* gK = g_K + tb * (NC * NS);
                #pragma unroll
                for (int i = 0; i < 16; ++i) {
                    float val = -acc[i];
                    sK[(r0 + i) * 64 + c] = val;
                    gK[(r0 + i) * 64 + c] = val;
                }
            } else {
                #pragma unroll
                for (int i = 0; i < 16; ++i) {
                    float val = -acc[i];
                    skv[r0 + i] = val;
                    g_k[tb * NC + r0 + i] = val;
                }
            }
        } else if (t > 0) {
            const float4* Fsrc = reinterpret_cast<const float4*>(
                Fg + ((size_t)(t - 1) * BATCH + b) * (NS * NN));
            float4* Fd = reinterpret_cast<float4*>(sF);
            for (int i = tid - 130; i < 1536; i += 126) Fd[i] = Fsrc[i];
        }
        __syncthreads();

        // ---- P6: Vn = Q_xx + sym(Q_xu K) via register pair-tiles | v_new ----
        if (u7bi >= 0) {
            const int i0 = u7bi * 4, j0 = u7bj * 4;
            if (u7bi == u7bj) {
                ull acc[4][2];
                #pragma unroll
                for (int u = 0; u < 4; ++u) { acc[u][0] = 0ull; acc[u][1] = 0ull; }
                #pragma unroll 4
                for (int r = 0; r < 32; ++r) {
                    float4 qa = *reinterpret_cast<const float4*>(&sQ[(64 + r) * 96 + i0]);
                    float4 kb = *reinterpret_cast<const float4*>(&sK[r * 64 + j0]);
                    ull k0 = pk2(kb.x, kb.y), k1 = pk2(kb.z, kb.w);
                    fma2(acc[0][0], dup2(qa.x), k0); fma2(acc[0][1], dup2(qa.x), k1);
                    fma2(acc[1][0], dup2(qa.y), k0); fma2(acc[1][1], dup2(qa.y), k1);
                    fma2(acc[2][0], dup2(qa.z), k0); fma2(acc[2][1], dup2(qa.z), k1);
                    fma2(acc[3][0], dup2(qa.w), k0); fma2(acc[3][1], dup2(qa.w), k1);
                }
                float U[4][4];
                #pragma unroll
                for (int u = 0; u < 4; ++u) {
                    upk2(U[u][0], U[u][1], acc[u][0]);
                    upk2(U[u][2], U[u][3], acc[u][1]);
                }
                #pragma unroll
                for (int u = 0; u < 4; ++u)
                    #pragma unroll
                    for (int v = 0; v < 4; ++v)
                        sV[(i0 + u) * 68 + j0 + v] =
                            sQ[(i0 + u) * 96 + j0 + v] + 0.5f * (U[u][v] + U[v][u]);
            } else {
                ull accA[4][2], accB[4][2];
                #pragma unroll
                for (int u = 0; u < 4; ++u) {
                    accA[u][0] = accA[u][1] = 0ull;
                    accB[u][0] = accB[u][1] = 0ull;
                }
                #pragma unroll 2
                for (int r = 0; r < 32; ++r) {
                    float4 qi = *reinterpret_cast<const float4*>(&sQ[(64 + r) * 96 + i0]);
                    float4 qj = *reinterpret_cast<const float4*>(&sQ[(64 + r) * 96 + j0]);
                    float4 ki = *reinterpret_cast<const float4*>(&sK[r * 64 + i0]);
                    float4 kj = *reinterpret_cast<const float4*>(&sK[r * 64 + j0]);
                    ull kj0 = pk2(kj.x, kj.y), kj1 = pk2(kj.z, kj.w);
                    ull ki0 = pk2(ki.x, ki.y), ki1 = pk2(ki.z, ki.w);
                    fma2(accA[0][0], dup2(qi.x), kj0); fma2(accA[0][1], dup2(qi.x), kj1);
                    fma2(accA[1][0], dup2(qi.y), kj0); fma2(accA[1][1], dup2(qi.y), kj1);
                    fma2(accA[2][0], dup2(qi.z), kj0); fma2(accA[2][1], dup2(qi.z), kj1);
                    fma2(accA[3][0], dup2(qi.w), kj0); fma2(accA[3][1], dup2(qi.w), kj1);
                    fma2(accB[0][0], dup2(qj.x), ki0); fma2(accB[0][1], dup2(qj.x), ki1);
                    fma2(accB[1][0], dup2(qj.y), ki0); fma2(accB[1][1], dup2(qj.y), ki1);
                    fma2(accB[2][0], dup2(qj.z), ki0); fma2(accB[2][1], dup2(qj.z), ki1);
                    fma2(accB[3][0], dup2(qj.w), ki0); fma2(accB[3][1], dup2(qj.w), ki1);
                }
                float A[4][4], B[4][4];
                #pragma unroll
                for (int u = 0; u < 4; ++u) {
                    upk2(A[u][0], A[u][1], accA[u][0]);
                    upk2(A[u][2], A[u][3], accA[u][1]);
                    upk2(B[u][0], B[u][1], accB[u][0]);
                    upk2(B[u][2], B[u][3], accB[u][1]);
                }
                #pragma unroll
                for (int u = 0; u < 4; ++u)
                    #pragma unroll
                    for (int v = 0; v < 4; ++v) {
                        float val = sQ[(i0 + u) * 96 + j0 + v]
                                  + 0.5f * (A[u][v] + B[v][u]);
                        sV[(i0 + u) * 68 + j0 + v] = val;
                        sV[(j0 + v) * 68 + i0 + u] = val;
                    }
            }
        } else if (tid >= 136 && tid < 200) {
            const int i = tid - 136;
            float s = sq[i] + sq2[i];
            #pragma unroll
            for (int r = 0; r < 32; ++r) s += sQ[(64 + r) * 96 + i] * skv[r];
            sv[i] = s;
        }
        __syncthreads();
    }

    // ================= FORWARD ROLLOUT (double-buffered) =================
    float* fx  = sm + OFF_FWD;        // x, 2 x 64
    float* fdx = fx  + 128;           // dx, 64
    float* fnu = fdx + 64;            // new_u, 32
    float* fk  = fnu + 32;            // k, 2 x 32
    float* fu  = fk  + 64;            // u, 2 x 32
    float* fxr = fu  + 64;            // xr, 2 x 64
    float* KB[2] = { sK, sZ };
    float* FB[2] = { sF, sQ };

    // preload t=0 buffers
    {
        const float4* Ks = reinterpret_cast<const float4*>(g_K + (size_t)b * (NC * NS));
        float4* Kd = reinterpret_cast<float4*>(KB[0]);
        for (int i = tid; i < 512; i += NTHR) Kd[i] = Ks[i];
        const float4* Fs = reinterpret_cast<const float4*>(Fg + (size_t)b * (NS * NN));
        float4* Fd = reinterpret_cast<float4*>(FB[0]);
        for (int i = tid; i < 1536; i += NTHR) Fd[i] = Fs[i];
        if (tid < 32) {
            fk[tid] = g_k[(size_t)b * NC + tid];
            fu[tid] = cug[(size_t)b * NC + tid];
        } else if (tid < 96) {
            int i = tid - 32;
            fxr[i] = cxg[((size_t)BATCH + b) * NS + i];   // cx[1]
        } else if (tid < 160) {
            int i = tid - 96;
            fx[i]  = x_init[(size_t)b * NS + i];
            fdx[i] = 0.f;
        }
    }
    __syncthreads();

    for (int t = 0; t < T_STEPS; ++t) {
        const int cur = t & 1, nxt = cur ^ 1;
        const size_t tb = (size_t)t * BATCH + b;

        // Phase A: new_u (0-127, quad-split) | prefetch t+1 + x output (128-255)
        if (tid < 128) {
            const int o = tid >> 2, seg = tid & 3;
            const float* Kb = KB[cur] + o * 64 + seg * 16;
            const float* dx = fdx + seg * 16;
            float s = 0.f;
            #pragma unroll
            for (int j = 0; j < 16; ++j) s += Kb[j] * dx[j];
            s += __shfl_xor_sync(0xffffffffu, s, 1);
            s += __shfl_xor_sync(0xffffffffu, s, 2);
            if (seg == 0) {
                float nu = s + fk[cur * 32 + o] + fu[cur * 32 + o];
                fnu[o] = nu;
                out[(size_t)T_STEPS * BATCH * NS + tb * NC + o] = nu;
            }
        } else {
            const int idx = tid - 128;
            if (idx < 64) out[tb * NS + idx] = fx[cur * 64 + idx];
            if (t + 1 < T_STEPS) {
                const size_t tb2 = tb + BATCH;
                const float4* Ks = reinterpret_cast<const float4*>(g_K + tb2 * (NC * NS));
                float4* Kd = reinterpret_cast<float4*>(KB[nxt]);
                for (int i = idx; i < 512; i += 128) Kd[i] = Ks[i];
                const float4* Fs = reinterpret_cast<const float4*>(Fg + tb2 * (NS * NN));
                float4* Fd = reinterpret_cast<float4*>(FB[nxt]);
                for (int i = idx; i < 1536; i += 128) Fd[i] = Fs[i];
                if (idx < 32) {
                    fk[nxt * 32 + idx] = g_k[tb2 * NC + idx];
                    fu[nxt * 32 + idx] = cug[tb2 * NC + idx];
                } else if (idx < 96) {
                    int i = idx - 32;
                    fxr[nxt * 64 + i] = (t + 2 < T_STEPS)
                        ? cxg[(tb2 + BATCH) * NS + i] : 0.f;
                }
            }
        }
        __syncthreads();

        // Phase B: x_next = F @ [x; new_u] (all 256, quad-split 24)
        {
            const int o = tid >> 2, seg = tid & 3;
            const float* Fr = FB[cur] + o * 96 + seg * 24;
            float s = 0.f;
            #pragma unroll
            for (int j = 0; j < 24; ++j) {
                int jj = seg * 24 + j;
                float xv = (jj < 64) ? fx[cur * 64 + jj] : fnu[jj - 64];
                s += Fr[j] * xv;
            }
            s += __shfl_xor_sync(0xffffffffu, s, 1);
            s += __shfl_xor_sync(0xffffffffu, s, 2);
            if (seg == 0) {
                fx[nxt * 64 + o] = s;
                fdx[o] = s - fxr[cur * 64 + o];
            }
        }
        __syncthreads();
    }
}

extern "C" void kernel_launch(void* const* d_in, const int* in_sizes, int n_in,
                              void* d_out, int out_size)
{
    const float* x_init = (const float*)d_in[0];
    const float* C      = (const float*)d_in[1];
    const float* c      = (const float*)d_in[2];
    const float* F      = (const float*)d_in[3];
    const float* cx     = (const float*)d_in[4];
    const float* cu     = (const float*)d_in[5];

    cudaFuncSetAttribute(lqr_kernel,
                         cudaFuncAttributeMaxDynamicSharedMemorySize, SMEM_BYTES);
    lqr_kernel<<<BATCH, NTHR, SMEM_BYTES>>>(x_init, C, c, F, cx, cu, (float*)d_out);
}

// round 10
// speedup vs baseline: 1.1267x; 1.1267x over previous
#include <cuda_runtime.h>

#define T_STEPS 50
#define BATCH   256
#define NS      64
#define NC      32
#define NN      96
#define NTHR    256

typedef unsigned long long ull;

__device__ float g_K[(size_t)T_STEPS * BATCH * NC * NS];   // [t][b][32][64]
__device__ float g_k[(size_t)T_STEPS * BATCH * NC];        // [t][b][32]

// ---- shared memory layout (floats) ----
#define OFF_V    0                       // V carry, 64 x 68 (symmetric)
#define OFF_F    (OFF_V  + 64*68)        // F tile, 64 x 96
#define OFF_Q    (OFF_F  + 6144)         // Q, 96 x 96 FULL (mirrored)
#define OFF_WB   (OFF_Q  + 9216)         // W (64x96) -- dead after phase 2
#define OFF_LI   (OFF_WB)                // Linv 32x33       (overlaps W)
#define OFF_Z    (OFF_LI + 1056)         // Z 32x65          (overlaps W)
#define OFF_K    (OFF_Z  + 2080)         // K 32x64          (overlaps W)
#define OFF_v    (OFF_WB + 6144)         // v carry, 64
#define OFF_q    (OFF_v  + 64)           // q part A, 96
#define OFF_q2   (OFF_q  + 96)           // q part B (F^T t), 96
#define OFF_xu   (OFF_q2 + 96)           // xut, 96
#define OFF_kv   (OFF_xu + 96)           // k vec, 32
#define OFF_T    (OFF_kv + 32)           // t = v - V z, 64
#define OFF_id   (OFF_T  + 64)           // inv diag, 32
#define OFF_zv   (OFF_id + 32)           // z = F xut, 64
#define OFF_L    (OFF_zv + 64)           // Cholesky 32x33 (DEDICATED)
#define OFF_FWD  (OFF_L  + 1056)         // forward-pass arrays (480)
#define SMEM_FLOATS (OFF_FWD + 480)
#define SMEM_BYTES  (SMEM_FLOATS * 4)

// ---- packed fp32x2 helpers (SASS FFMA2 path) ----
__device__ __forceinline__ ull pk2(float lo, float hi) {
    ull r; asm("mov.b64 %0, {%1, %2};" : "=l"(r) : "f"(lo), "f"(hi)); return r;
}
__device__ __forceinline__ ull dup2(float x) { return pk2(x, x); }
__device__ __forceinline__ void upk2(float& lo, float& hi, ull v) {
    asm("mov.b64 {%0, %1}, %2;" : "=f"(lo), "=f"(hi) : "l"(v));
}
__device__ __forceinline__ void fma2(ull& d, ull a, ull b) {
    asm("fma.rn.f32x2 %0, %2, %3, %1;" : "=l"(d) : "l"(d), "l"(a), "l"(b));
}

__global__ __launch_bounds__(NTHR, 2)
void lqr_kernel(const float* __restrict__ x_init,
                const float* __restrict__ Cg,
                const float* __restrict__ cg,
                const float* __restrict__ Fg,
                const float* __restrict__ cxg,
                const float* __restrict__ cug,
                float* __restrict__ out)
{
    extern __shared__ float sm[];
    const int b   = blockIdx.x;
    const int tid = threadIdx.x;

    float* sV  = sm + OFF_V;
    float* sF  = sm + OFF_F;
    float* sQ  = sm + OFF_Q;
    float* sW  = sm + OFF_WB;
    float* sLi = sm + OFF_LI;
    float* sZ  = sm + OFF_Z;
    float* sK  = sm + OFF_K;
    float* sv  = sm + OFF_v;
    float* sq  = sm + OFF_q;
    float* sq2 = sm + OFF_q2;
    float* sxu = sm + OFF_xu;
    float* skv = sm + OFF_kv;
    float* st  = sm + OFF_T;
    float* sid = sm + OFF_id;
    float* sz  = sm + OFF_zv;
    float* sL  = sm + OFF_L;

    // Phase-2 job map: 6x8 tiles over 96x96, lower blocks (6bi+5 >= 8bj): 108 jobs.
    int p2bi = -1, p2bj = 0;
    {
        int idx = tid;
        #pragma unroll
        for (int r = 0; r < 16; ++r) {
            int cnt = (6 * r + 5) / 8 + 1;
            if (idx < cnt && p2bi < 0) { p2bi = r; p2bj = idx; }
            if (p2bi < 0) idx -= cnt;
        }
    }
    const bool p2a = (p2bi >= 0);

    // Phase-6 pair-tile map: 4x4 tiles on 64x64, (bi>=bj): 136 jobs.
    int u7bi = -1, u7bj = 0;
    {
        int idx = tid;
        #pragma unroll
        for (int r = 0; r < 16; ++r) {
            int cnt = r + 1;
            if (idx < cnt && u7bi < 0) { u7bi = r; u7bj = idx; }
            if (u7bi < 0) idx -= cnt;
        }
    }

    // ---------------- init ----------------
    for (int i = tid; i < 64 * 68; i += NTHR) sV[i] = 0.f;
    if (tid < NS) sv[tid] = 0.f;
    {
        const float* Fsrc = Fg + ((size_t)(T_STEPS - 1) * BATCH + b) * (NS * NN);
        for (int i = tid; i < NS * NN; i += NTHR) sF[i] = Fsrc[i];
    }
    __syncthreads();

    // ================= BACKWARD RICCATI SCAN =================
    for (int t = T_STEPS - 1; t >= 0; --t) {
        const size_t tb = (size_t)t * BATCH + b;

        // ---- P1: W = V @ F (64x96), 4x12 FFMA2 tiles (tid<128)
        //      | xut -> z = F@xut -> t = v - V@z  (tid>=128, internal bars) ----
        if (tid < 128) {
            const int i0 = (tid >> 3) * 4;      // 16 row-blocks
            const int j0 = (tid & 7) * 12;      // 8 col-blocks
            ull acc[4][6];
            #pragma unroll
            for (int u = 0; u < 4; ++u)
                #pragma unroll
                for (int p = 0; p < 6; ++p) acc[u][p] = 0ull;
            #pragma unroll 2
            for (int a = 0; a < 64; ++a) {
                float4 b0 = *reinterpret_cast<const float4*>(&sF[a * 96 + j0]);
                float4 b1 = *reinterpret_cast<const float4*>(&sF[a * 96 + j0 + 4]);
                float4 b2 = *reinterpret_cast<const float4*>(&sF[a * 96 + j0 + 8]);
                ull bv[6] = { pk2(b0.x, b0.y), pk2(b0.z, b0.w),
                              pk2(b1.x, b1.y), pk2(b1.z, b1.w),
                              pk2(b2.x, b2.y), pk2(b2.z, b2.w) };
                float4 av = *reinterpret_cast<const float4*>(&sV[a * 68 + i0]); // V sym
                ull a0 = dup2(av.x), a1 = dup2(av.y), a2 = dup2(av.z), a3 = dup2(av.w);
                #pragma unroll
                for (int p = 0; p < 6; ++p) {
                    fma2(acc[0][p], a0, bv[p]); fma2(acc[1][p], a1, bv[p]);
                    fma2(acc[2][p], a2, bv[p]); fma2(acc[3][p], a3, bv[p]);
                }
            }
            #pragma unroll
            for (int u = 0; u < 4; ++u)
                #pragma unroll
                for (int p = 0; p < 6; ++p)
                    *reinterpret_cast<ull*>(&sW[(i0 + u) * 96 + j0 + 2 * p]) = acc[u][p];
        } else {
            const int idx = tid - 128;
            if (idx < NS)            sxu[idx] = cxg[tb * NS + idx];
            else if (idx < NN)       sxu[idx] = cug[tb * NC + (idx - NS)];
            asm volatile("bar.sync 3, 128;" ::: "memory");   // warps 4-7 only
            if (idx < 64) {
                const int o = idx;
                int ro = (3 * o) % 96;
                float s0 = 0.f, s1 = 0.f;
                #pragma unroll 8
                for (int j = 0; j < 96; j += 2) {
                    int j0i = j + ro;     if (j0i >= 96) j0i -= 96;
                    int j1i = j + 1 + ro; if (j1i >= 96) j1i -= 96;
                    s0 += sF[o * 96 + j0i] * sxu[j0i];
                    s1 += sF[o * 96 + j1i] * sxu[j1i];
                }
                sz[o] = s0 + s1;
            }
            asm volatile("bar.sync 3, 128;" ::: "memory");
            if (idx < 64) {
                const int a = idx;
                const int ra = (3 * a) & 63;
                float s0 = 0.f, s1 = 0.f;
                #pragma unroll 8
                for (int j = 0; j < 64; j += 2) {
                    int j0i = (j + ra) & 63;
                    int j1i = (j + 1 + ra) & 63;
                    s0 += sV[a * 68 + j0i] * sz[j0i];
                    s1 += sV[a * 68 + j1i] * sz[j1i];
                }
                st[a] = sv[a] - s0 - s1;
            }
        }
        __syncthreads();

        // ---- P2: Q = C + F^T W (lower 6x8 + mirror), dual-write Quu -> sL ----
        if (p2a) {
            const int i0 = p2bi * 6, j0 = p2bj * 8;
            const float* Crow = Cg + tb * (NN * NN);
            float4 cL[6][2];
            #pragma unroll
            for (int r = 0; r < 6; ++r) {
                cL[r][0] = *reinterpret_cast<const float4*>(&Crow[(i0 + r) * 96 + j0]);
                cL[r][1] = *reinterpret_cast<const float4*>(&Crow[(i0 + r) * 96 + j0 + 4]);
            }
            ull acc[3][8];
            #pragma unroll
            for (int m = 0; m < 3; ++m)
                #pragma unroll
                for (int v = 0; v < 8; ++v) acc[m][v] = 0ull;
            #pragma unroll 2
            for (int a = 0; a < 64; ++a) {
                ull am[3];
                #pragma unroll
                for (int m = 0; m < 3; ++m)
                    am[m] = *reinterpret_cast<const ull*>(&sF[a * 96 + i0 + 2 * m]);
                float4 w0 = *reinterpret_cast<const float4*>(&sW[a * 96 + j0]);
                float4 w1 = *reinterpret_cast<const float4*>(&sW[a * 96 + j0 + 4]);
                ull wd[8] = { dup2(w0.x), dup2(w0.y), dup2(w0.z), dup2(w0.w),
                              dup2(w1.x), dup2(w1.y), dup2(w1.z), dup2(w1.w) };
                #pragma unroll
                for (int m = 0; m < 3; ++m)
                    #pragma unroll
                    for (int v = 0; v < 8; ++v) fma2(acc[m][v], am[m], wd[v]);
            }
            #pragma unroll
            for (int m = 0; m < 3; ++m) {
                float r0[8], r1[8];
                #pragma unroll
                for (int v = 0; v < 8; ++v) upk2(r0[v], r1[v], acc[m][v]);
                const float* c0a = &cL[2 * m][0].x;
                const float* c1a = &cL[2 * m + 1][0].x;
                #pragma unroll
                for (int v = 0; v < 8; ++v) {
                    const int i = i0 + 2 * m, j = j0 + v;
                    float val = r0[v] + c0a[v];
                    if (i >= j) {
                        sQ[i * 96 + j] = val;
                        if (j >= 64) sL[(i - 64) * 33 + (j - 64)] = val;
                    }
                    if (i > j) {
                        sQ[j * 96 + i] = val;
                        if (j >= 64) sL[(j - 64) * 33 + (i - 64)] = val;
                    }
                }
                #pragma unroll
                for (int v = 0; v < 8; ++v) {
                    const int i = i0 + 2 * m + 1, j = j0 + v;
                    float val = r1[v] + c1a[v];
                    if (i >= j) {
                        sQ[i * 96 + j] = val;
                        if (j >= 64) sL[(i - 64) * 33 + (j - 64)] = val;
                    }
                    if (i > j) {
                        sQ[j * 96 + i] = val;
                        if (j >= 64) sL[(j - 64) * 33 + (i - 64)] = val;
                    }
                }
            }
        }
        __syncthreads();

        // ---- P3: qA = c + Q@xut (0-95) | Chol+Linv (warp 4) | qB = F^T t (160-255) ----
        if (tid < NN) {
            const int i = tid;
            float cval = cg[tb * NN + i];
            float s0 = 0.f, s1 = 0.f, s2 = 0.f, s3 = 0.f;
            #pragma unroll 8
            for (int j = 0; j < 96; j += 4) {
                int j0i = j + i;     if (j0i >= 96) j0i -= 96;
                int j1i = j + 1 + i; if (j1i >= 96) j1i -= 96;
                int j2i = j + 2 + i; if (j2i >= 96) j2i -= 96;
                int j3i = j + 3 + i; if (j3i >= 96) j3i -= 96;
                s0 += sQ[i * 96 + j0i] * sxu[j0i];
                s1 += sQ[i * 96 + j1i] * sxu[j1i];
                s2 += sQ[i * 96 + j2i] * sxu[j2i];
                s3 += sQ[i * 96 + j3i] * sxu[j3i];
            }
            sq[i] = cval + (s0 + s1) + (s2 + s3);
        } else if (tid >= 128 && tid < 160) {
            const int r = tid - 128;
            float Lr[32];
            #pragma unroll
            for (int kk = 0; kk < 32; ++kk) Lr[kk] = sL[r * 33 + kk];
            #pragma unroll
            for (int j = 0; j < 32; ++j) {
                // quad-accumulator dot: dependent chain ~j/4
                float a0 = Lr[j], a1 = 0.f, a2 = 0.f, a3 = 0.f;
                int kk = 0;
                #pragma unroll
                for (; kk + 3 < j; kk += 4) {
                    a0 -= Lr[kk]     * sL[j * 33 + kk];
                    a1 -= Lr[kk + 1] * sL[j * 33 + kk + 1];
                    a2 -= Lr[kk + 2] * sL[j * 33 + kk + 2];
                    a3 -= Lr[kk + 3] * sL[j * 33 + kk + 3];
                }
                #pragma unroll
                for (; kk < j; ++kk) a0 -= Lr[kk] * sL[j * 33 + kk];
                float s = (a0 + a1) + (a2 + a3);
                float sj = __shfl_sync(0xffffffffu, s, j);
                float inv = rsqrtf(sj);
                float d = sj * inv;                      // = sqrt(sj)
                float val = (r == j) ? d : s * inv;
                Lr[j] = val;
                if (r >= j) sL[r * 33 + j] = val;
                if (r == j) sid[j] = inv;                // 1/sqrt = 1/d
                __syncwarp();
            }
            // triangular inverse: lane r computes column r of Linv
            {
                float x[32];
                #pragma unroll
                for (int j = 0; j < 32; ++j) {
                    float a0 = (j == r) ? 1.0f : 0.0f, a1 = 0.f, a2 = 0.f, a3 = 0.f;
                    int kk = 0;
                    #pragma unroll
                    for (; kk + 3 < j; kk += 4) {
                        a0 -= sL[j * 33 + kk]     * x[kk];
                        a1 -= sL[j * 33 + kk + 1] * x[kk + 1];
                        a2 -= sL[j * 33 + kk + 2] * x[kk + 2];
                        a3 -= sL[j * 33 + kk + 3] * x[kk + 3];
                    }
                    #pragma unroll
                    for (; kk < j; ++kk) a0 -= sL[j * 33 + kk] * x[kk];
                    x[j] = (j < r) ? 0.0f : ((a0 + a1) + (a2 + a3)) * sid[j];
                    sLi[j * 33 + r] = x[j];
                }
            }
        } else if (tid >= 160) {
            const int i = tid - 160;
            float f0 = 0.f, f1 = 0.f;
            #pragma unroll 8
            for (int a = 0; a < 64; a += 2) {
                f0 += sF[a * 96 + i] * st[a];
                f1 += sF[(a + 1) * 96 + i] * st[a + 1];
            }
            sq2[i] = f0 + f1;
        }
        __syncthreads();

        // ---- P4: Z = Linv @ [Q_ux | q_u] (tid<130) | F-prefetch 1/2 (160-255) ----
        if (tid < 130) {
            const int c  = tid % 65;
            const int r0 = (tid / 65) * 16;
            float acc[16];
            #pragma unroll
            for (int rr = 0; rr < 16; ++rr) acc[rr] = 0.f;
            #pragma unroll 4
            for (int j = 0; j < 32; ++j) {
                float rv = (c < 64) ? sQ[(64 + j) * 96 + c]
                                    : (sq[64 + j] + sq2[64 + j]);
                #pragma unroll
                for (int rr = 0; rr < 16; ++rr)
                    acc[rr] += sLi[(r0 + rr) * 33 + j] * rv;
            }
            #pragma unroll
            for (int rr = 0; rr < 16; ++rr) sZ[(r0 + rr) * 65 + c] = acc[rr];
        } else if (tid >= 160 && t > 0) {
            const float4* Fsrc = reinterpret_cast<const float4*>(
                Fg + ((size_t)(t - 1) * BATCH + b) * (NS * NN));
            float4* Fd = reinterpret_cast<float4*>(sF);
            for (int i = tid - 160; i < 768; i += 96) Fd[i] = Fsrc[i];
        }
        __syncthreads();

        // ---- P5: K = -Linv^T @ Z -> sK,gK,skv,g_k | F-prefetch 2/2 ----
        if (tid < 130) {
            const int c  = tid % 65;
            const int r0 = (tid / 65) * 16;
            float acc[16];
            #pragma unroll
            for (int rr = 0; rr < 16; ++rr) acc[rr] = 0.f;
            #pragma unroll 4
            for (int j = 0; j < 32; ++j) {
                float zv = sZ[j * 65 + c];
                #pragma unroll
                for (int rr = 0; rr < 16; ++rr)
                    acc[rr] += sLi[j * 33 + r0 + rr] * zv;
            }
            if (c < 64) {
                float* gK = g_K + tb * (NC * NS);
                #pragma unroll
                for (int rr = 0; rr < 16; ++rr) {
                    float val = -acc[rr];
                    sK[(r0 + rr) * 64 + c] = val;
                    gK[(r0 + rr) * 64 + c] = val;
                }
            } else {
                #pragma unroll
                for (int rr = 0; rr < 16; ++rr) {
                    float val = -acc[rr];
                    skv[r0 + rr] = val;
                    g_k[tb * NC + r0 + rr] = val;
                }
            }
        } else if (tid >= 160 && t > 0) {
            const float4* Fsrc = reinterpret_cast<const float4*>(
                Fg + ((size_t)(t - 1) * BATCH + b) * (NS * NN));
            float4* Fd = reinterpret_cast<float4*>(sF);
            for (int i = 768 + (tid - 160); i < 1536; i += 96) Fd[i] = Fsrc[i];
        }
        __syncthreads();

        // ---- P6: Vn = Q_xx + sym(Q_xu K) via register pair-tiles | v_new ----
        if (u7bi >= 0) {
            const int i0 = u7bi * 4, j0 = u7bj * 4;
            if (u7bi == u7bj) {
                ull acc[4][2];
                #pragma unroll
                for (int u = 0; u < 4; ++u) { acc[u][0] = 0ull; acc[u][1] = 0ull; }
                #pragma unroll 4
                for (int r = 0; r < 32; ++r) {
                    float4 qa = *reinterpret_cast<const float4*>(&sQ[(64 + r) * 96 + i0]);
                    float4 kb = *reinterpret_cast<const float4*>(&sK[r * 64 + j0]);
                    ull k0 = pk2(kb.x, kb.y), k1 = pk2(kb.z, kb.w);
                    fma2(acc[0][0], dup2(qa.x), k0); fma2(acc[0][1], dup2(qa.x), k1);
                    fma2(acc[1][0], dup2(qa.y), k0); fma2(acc[1][1], dup2(qa.y), k1);
                    fma2(acc[2][0], dup2(qa.z), k0); fma2(acc[2][1], dup2(qa.z), k1);
                    fma2(acc[3][0], dup2(qa.w), k0); fma2(acc[3][1], dup2(qa.w), k1);
                }
                float U[4][4];
                #pragma unroll
                for (int u = 0; u < 4; ++u) {
                    upk2(U[u][0], U[u][1], acc[u][0]);
                    upk2(U[u][2], U[u][3], acc[u][1]);
                }
                #pragma unroll
                for (int u = 0; u < 4; ++u)
                    #pragma unroll
                    for (int v = 0; v < 4; ++v)
                        sV[(i0 + u) * 68 + j0 + v] =
                            sQ[(i0 + u) * 96 + j0 + v] + 0.5f * (U[u][v] + U[v][u]);
            } else {
                ull accA[4][2], accB[4][2];
                #pragma unroll
                for (int u = 0; u < 4; ++u) {
                    accA[u][0] = accA[u][1] = 0ull;
                    accB[u][0] = accB[u][1] = 0ull;
                }
                #pragma unroll 2
                for (int r = 0; r < 32; ++r) {
                    float4 qi = *reinterpret_cast<const float4*>(&sQ[(64 + r) * 96 + i0]);
                    float4 qj = *reinterpret_cast<const float4*>(&sQ[(64 + r) * 96 + j0]);
                    float4 ki = *reinterpret_cast<const float4*>(&sK[r * 64 + i0]);
                    float4 kj = *reinterpret_cast<const float4*>(&sK[r * 64 + j0]);
                    ull kj0 = pk2(kj.x, kj.y), kj1 = pk2(kj.z, kj.w);
                    ull ki0 = pk2(ki.x, ki.y), ki1 = pk2(ki.z, ki.w);
                    fma2(accA[0][0], dup2(qi.x), kj0); fma2(accA[0][1], dup2(qi.x), kj1);
                    fma2(accA[1][0], dup2(qi.y), kj0); fma2(accA[1][1], dup2(qi.y), kj1);
                    fma2(accA[2][0], dup2(qi.z), kj0); fma2(accA[2][1], dup2(qi.z), kj1);
                    fma2(accA[3][0], dup2(qi.w), kj0); fma2(accA[3][1], dup2(qi.w), kj1);
                    fma2(accB[0][0], dup2(qj.x), ki0); fma2(accB[0][1], dup2(qj.x), ki1);
                    fma2(accB[1][0], dup2(qj.y), ki0); fma2(accB[1][1], dup2(qj.y), ki1);
                    fma2(accB[2][0], dup2(qj.z), ki0); fma2(accB[2][1], dup2(qj.z), ki1);
                    fma2(accB[3][0], dup2(qj.w), ki0); fma2(accB[3][1], dup2(qj.w), ki1);
                }
                float A[4][4], B[4][4];
                #pragma unroll
                for (int u = 0; u < 4; ++u) {
                    upk2(A[u][0], A[u][1], accA[u][0]);
                    upk2(A[u][2], A[u][3], accA[u][1]);
                    upk2(B[u][0], B[u][1], accB[u][0]);
                    upk2(B[u][2], B[u][3], accB[u][1]);
                }
                #pragma unroll
                for (int u = 0; u < 4; ++u)
                    #pragma unroll
                    for (int v = 0; v < 4; ++v) {
                        float val = sQ[(i0 + u) * 96 + j0 + v]
                                  + 0.5f * (A[u][v] + B[v][u]);
                        sV[(i0 + u) * 68 + j0 + v] = val;
                        sV[(j0 + v) * 68 + i0 + u] = val;
                    }
            }
        } else if (tid >= 136 && tid < 200) {
            const int i = tid - 136;
            float s = sq[i] + sq2[i];
            #pragma unroll
            for (int r = 0; r < 32; ++r) s += sQ[(64 + r) * 96 + i] * skv[r];
            sv[i] = s;
        }
        __syncthreads();
    }

    // ================= FORWARD ROLLOUT (double-buffered) =================
    float* fx  = sm + OFF_FWD;        // x, 2 x 64
    float* fdx = fx  + 128;           // dx, 64
    float* fnu = fdx + 64;            // new_u, 32
    float* fk  = fnu + 32;            // k, 2 x 32
    float* fu  = fk  + 64;            // u, 2 x 32
    float* fxr = fu  + 64;            // xr, 2 x 64
    float* KB[2] = { sK, sZ };
    float* FB[2] = { sF, sQ };

    // preload t=0 buffers
    {
        const float4* Ks = reinterpret_cast<const float4*>(g_K + (size_t)b * (NC * NS));
        float4* Kd = reinterpret_cast<float4*>(KB[0]);
        for (int i = tid; i < 512; i += NTHR) Kd[i] = Ks[i];
        const float4* Fs = reinterpret_cast<const float4*>(Fg + (size_t)b * (NS * NN));
        float4* Fd = reinterpret_cast<float4*>(FB[0]);
        for (int i = tid; i < 1536; i += NTHR) Fd[i] = Fs[i];
        if (tid < 32) {
            fk[tid] = g_k[(size_t)b * NC + tid];
            fu[tid] = cug[(size_t)b * NC + tid];
        } else if (tid < 96) {
            int i = tid - 32;
            fxr[i] = cxg[((size_t)BATCH + b) * NS + i];   // cx[1]
        } else if (tid < 160) {
            int i = tid - 96;
            fx[i]  = x_init[(size_t)b * NS + i];
            fdx[i] = 0.f;
        }
    }
    __syncthreads();

    for (int t = 0; t < T_STEPS; ++t) {
        const int cur = t & 1, nxt = cur ^ 1;
        const size_t tb = (size_t)t * BATCH + b;

        // Phase A: new_u (0-127, quad-split) | prefetch t+1 + x output (128-255)
        if (tid < 128) {
            const int o = tid >> 2, seg = tid & 3;
            const float* Kb = KB[cur] + o * 64 + seg * 16;
            const float* dx = fdx + seg * 16;
            float s = 0.f;
            #pragma unroll
            for (int j = 0; j < 16; ++j) s += Kb[j] * dx[j];
            s += __shfl_xor_sync(0xffffffffu, s, 1);
            s += __shfl_xor_sync(0xffffffffu, s, 2);
            if (seg == 0) {
                float nu = s + fk[cur * 32 + o] + fu[cur * 32 + o];
                fnu[o] = nu;
                out[(size_t)T_STEPS * BATCH * NS + tb * NC + o] = nu;
            }
        } else {
            const int idx = tid - 128;
            if (idx < 64) out[tb * NS + idx] = fx[cur * 64 + idx];
            if (t + 1 < T_STEPS) {
                const size_t tb2 = tb + BATCH;
                const float4* Ks = reinterpret_cast<const float4*>(g_K + tb2 * (NC * NS));
                float4* Kd = reinterpret_cast<float4*>(KB[nxt]);
                for (int i = idx; i < 512; i += 128) Kd[i] = Ks[i];
                const float4* Fs = reinterpret_cast<const float4*>(Fg + tb2 * (NS * NN));
                float4* Fd = reinterpret_cast<float4*>(FB[nxt]);
                for (int i = idx; i < 1536; i += 128) Fd[i] = Fs[i];
                if (idx < 32) {
                    fk[nxt * 32 + idx] = g_k[tb2 * NC + idx];
                    fu[nxt * 32 + idx] = cug[tb2 * NC + idx];
                } else if (idx < 96) {
                    int i = idx - 32;
                    fxr[nxt * 64 + i] = (t + 2 < T_STEPS)
                        ? cxg[(tb2 + BATCH) * NS + i] : 0.f;
                }
            }
        }
        __syncthreads();

        // Phase B: x_next = F @ [x; new_u] (all 256, quad-split 24)
        {
            const int o = tid >> 2, seg = tid & 3;
            const float* Fr = FB[cur] + o * 96 + seg * 24;
            float s = 0.f;
            #pragma unroll
            for (int j = 0; j < 24; ++j) {
                int jj = seg * 24 + j;
                float xv = (jj < 64) ? fx[cur * 64 + jj] : fnu[jj - 64];
                s += Fr[j] * xv;
            }
            s += __shfl_xor_sync(0xffffffffu, s, 1);
            s += __shfl_xor_sync(0xffffffffu, s, 2);
            if (seg == 0) {
                fx[nxt * 64 + o] = s;
                fdx[o] = s - fxr[cur * 64 + o];
            }
        }
        __syncthreads();
    }
}

extern "C" void kernel_launch(void* const* d_in, const int* in_sizes, int n_in,
                              void* d_out, int out_size)
{
    const float* x_init = (const float*)d_in[0];
    const float* C      = (const float*)d_in[1];
    const float* c      = (const float*)d_in[2];
    const float* F      = (const float*)d_in[3];
    const float* cx     = (const float*)d_in[4];
    const float* cu     = (const float*)d_in[5];

    cudaFuncSetAttribute(lqr_kernel,
                         cudaFuncAttributeMaxDynamicSharedMemorySize, SMEM_BYTES);
    lqr_kernel<<<BATCH, NTHR, SMEM_BYTES>>>(x_init, C, c, F, cx, cu, (float*)d_out);
}